// round 1
// baseline (speedup 1.0000x reference)
#include <cuda_runtime.h>

// Micromagnetic LLG RK4 solver, persistent-kernel formulation.
// Grid state: m[3][256][256] f32. 100 relax steps (alpha=0.5) then
// 2 signals x 256 driven steps (alpha=0.01) with 3 source cells and 5 probes.
// One thread owns one cell for the whole kernel; RK4 accumulator, base m,
// B_ext and m_relaxed stay in registers. Stages communicate via 3 global
// ping-pong buffers with a hand-rolled sense-reversal grid barrier
// (all 256 CTAs provably co-resident on 148 SMs).

#define NXg 256
#define NYg 256
#define PLANE (NXg * NYg)
#define TSTEPS 256
#define NSIG 2
#define NSRC 3
#define NPROBE 5
#define RELAXN 100
#define NBLK 256
#define NTHR 256

__device__ float g_m [3 * PLANE];
__device__ float g_ta[3 * PLANE];
__device__ float g_tb[3 * PLANE];
__device__ unsigned g_cnt = 0;
__device__ volatile unsigned g_gen = 0;

// CG-style grid barrier: fence -> elected atomic arrive -> sense-reversal
// spin on generation counter -> fence. Self-resetting via atomicInc wrap.
__device__ __forceinline__ void gridbar() {
    __syncthreads();
    if (threadIdx.x == 0) {
        __threadfence();
        unsigned gen = g_gen;
        if (atomicInc(&g_cnt, NBLK - 1u) == NBLK - 1u) {
            g_gen = gen + 1u;
        } else {
            while (g_gen == gen) { }
        }
        __threadfence();
    }
    __syncthreads();
}

struct Ctx {
    int idx, iN, iS, iW, iE;
    float bx, by, bz;       // B_ext at own cell
    float CEx, CD, hh;
};

// LLG torque at own cell. Own stage-input value (ux,uy,uz) is in registers;
// 4 neighbors per component loaded with .cg (L2-coherent, no stale L1 risk).
__device__ __forceinline__ void torque(const float* __restrict__ in, const Ctx& c,
                                       float ux, float uy, float uz,
                                       float bzAdd, float alpha, float inv,
                                       float& tx, float& ty, float& tz)
{
    float lx = __ldcg(in + c.iN) + __ldcg(in + c.iS)
             + __ldcg(in + c.iW) + __ldcg(in + c.iE) - 4.0f * ux;
    float ly = __ldcg(in + PLANE + c.iN) + __ldcg(in + PLANE + c.iS)
             + __ldcg(in + PLANE + c.iW) + __ldcg(in + PLANE + c.iE) - 4.0f * uy;
    float lz = __ldcg(in + 2 * PLANE + c.iN) + __ldcg(in + 2 * PLANE + c.iS)
             + __ldcg(in + 2 * PLANE + c.iW) + __ldcg(in + 2 * PLANE + c.iE) - 4.0f * uz;

    float Bx = c.bx + c.CEx * lx;
    float By = c.by + c.CEx * ly;
    float Bz = c.bz + bzAdd + c.CEx * lz - c.CD * uz;

    // c1 = u x B
    float c1x = uy * Bz - uz * By;
    float c1y = uz * Bx - ux * Bz;
    float c1z = ux * By - uy * Bx;
    // c2 = u x c1
    float c2x = uy * c1z - uz * c1y;
    float c2y = uz * c1x - ux * c1z;
    float c2z = ux * c1y - uy * c1x;
    // sot = C_SOT * (u x (u x p)), p=(0,1,0)  ->  (ux*uy, -(uz^2+ux^2), uy*uz)
    const float CS = 1.0e-4f;
    tx = -inv * (c1x + alpha * c2x) + CS * (ux * uy);
    ty = -inv * (c1y + alpha * c2y) + CS * (-(uz * uz + ux * ux));
    tz = -inv * (c1z + alpha * c2z) + CS * (uy * uz);
}

__device__ __forceinline__ void store3(float* __restrict__ buf, int idx,
                                       float x, float y, float z) {
    __stcg(buf + idx, x);
    __stcg(buf + PLANE + idx, y);
    __stcg(buf + 2 * PLANE + idx, z);
}

// One full RK4 step with 4 grid barriers. m (own cell) updated in registers
// and written back to g_m.
__device__ __forceinline__ void rk4(float& mx, float& my_, float& mz,
                                    const Ctx& c, float bzAdd,
                                    float alpha, float inv)
{
    float kx, ky, kz;
    // stage 1 : input g_m (own value = registers)
    torque(g_m, c, mx, my_, mz, bzAdd, alpha, inv, kx, ky, kz);
    float ax = kx, ay = ky, az = kz;
    float h2 = 0.5f * c.hh;
    float ux = mx + h2 * kx, uy = my_ + h2 * ky, uz = mz + h2 * kz;
    store3(g_ta, c.idx, ux, uy, uz);
    gridbar();
    // stage 2 : input g_ta
    torque(g_ta, c, ux, uy, uz, bzAdd, alpha, inv, kx, ky, kz);
    ax += 2.0f * kx; ay += 2.0f * ky; az += 2.0f * kz;
    ux = mx + h2 * kx; uy = my_ + h2 * ky; uz = mz + h2 * kz;
    store3(g_tb, c.idx, ux, uy, uz);
    gridbar();
    // stage 3 : input g_tb
    torque(g_tb, c, ux, uy, uz, bzAdd, alpha, inv, kx, ky, kz);
    ax += 2.0f * kx; ay += 2.0f * ky; az += 2.0f * kz;
    ux = mx + c.hh * kx; uy = my_ + c.hh * ky; uz = mz + c.hh * kz;
    store3(g_ta, c.idx, ux, uy, uz);
    gridbar();
    // stage 4 : input g_ta
    torque(g_ta, c, ux, uy, uz, bzAdd, alpha, inv, kx, ky, kz);
    float h6 = c.hh * (1.0f / 6.0f);
    mx = mx + h6 * (ax + kx);
    my_ = my_ + h6 * (ay + ky);
    mz = mz + h6 * (az + kz);
    store3(g_m, c.idx, mx, my_, mz);
    gridbar();
}

__global__ void __launch_bounds__(NTHR, 2)
mm_kernel(const float* __restrict__ sig, const float* __restrict__ Bext,
          const float* __restrict__ MsatP, const int* __restrict__ srcP,
          const int* __restrict__ probeP, const int* __restrict__ finalP,
          float* __restrict__ out)
{
    const int r = blockIdx.x;
    const int cc = threadIdx.x;

    Ctx c;
    c.idx = r * NYg + cc;
    {
        int rN = (r > 0) ? r - 1 : 0;
        int rS = (r < NXg - 1) ? r + 1 : NXg - 1;
        int cW = (cc > 0) ? cc - 1 : 0;
        int cE = (cc < NYg - 1) ? cc + 1 : NYg - 1;
        c.iN = rN * NYg + cc;
        c.iS = rS * NYg + cc;
        c.iW = r * NYg + cW;
        c.iE = r * NYg + cE;
    }

    const float Msat = *MsatP;
    c.CEx = (float)(2.0 * 3.5e-12 / ((double)Msat * (5e-8 * 5e-8)));
    c.CD  = (float)(4e-7 * 3.14159265358979323846 * (double)Msat);
    c.hh  = (float)(175950000000.0 * 5e-12);   // GAMMA_LL * DT = 0.87975
    const int final_board = *finalP;

    c.bx = Bext[0 * PLANE + c.idx];
    c.by = Bext[1 * PLANE + c.idx];
    c.bz = Bext[2 * PLANE + c.idx];

    int my_src = -1, my_probe = -1;
    #pragma unroll
    for (int k = 0; k < NSRC; k++)
        if (srcP[2 * k] == r && srcP[2 * k + 1] == cc) my_src = k;
    #pragma unroll
    for (int k = 0; k < NPROBE; k++)
        if (probeP[2 * k] == r && probeP[2 * k + 1] == cc) my_probe = k;

    // m0 = (0, 1, 0)
    float mx = 0.0f, my_ = 1.0f, mz = 0.0f;
    store3(g_m, c.idx, mx, my_, mz);
    gridbar();

    // ---- relax phase: alpha = 0.5, no source ----
    {
        const float alpha = 0.5f;
        const float inv = 1.0f / (1.0f + alpha * alpha);
        for (int s = 0; s < RELAXN; s++)
            rk4(mx, my_, mz, c, 0.0f, alpha, inv);
    }
    const float rx = mx, ry = my_, rz = mz;   // m_relaxed (own cell)

    // ---- driven phase: alpha = 0.01, per-signal restart from m_relaxed ----
    {
        const float alpha = 0.01f;
        const float inv = 1.0f / (1.0f + alpha * alpha);
        for (int sgn = 0; sgn < NSIG; sgn++) {
            mx = rx; my_ = ry; mz = rz;
            store3(g_m, c.idx, mx, my_, mz);
            gridbar();
            for (int t = 0; t < TSTEPS; t++) {
                float bzAdd = (my_src >= 0)
                    ? sig[(sgn * TSTEPS + t) * NSRC + my_src] : 0.0f;
                rk4(mx, my_, mz, c, bzAdd, alpha, inv);
                if (my_probe >= 0) {
                    float val = final_board ? (mz - rz) * Msat : mz;
                    out[(sgn * TSTEPS + t) * NPROBE + my_probe] = val;
                }
            }
        }
    }
}

extern "C" void kernel_launch(void* const* d_in, const int* in_sizes, int n_in,
                              void* d_out, int out_size) {
    const float* sig    = (const float*)d_in[0];  // (2, 256, 3)
    const float* Bext   = (const float*)d_in[1];  // (1, 3, 256, 256)
    const float* MsatP  = (const float*)d_in[2];  // scalar
    const int*   srcP   = (const int*)d_in[3];    // (3, 2)
    const int*   probeP = (const int*)d_in[4];    // (5, 2)
    const int*   finalP = (const int*)d_in[5];    // scalar
    float* out = (float*)d_out;                   // (2, 256, 5)
    (void)in_sizes; (void)n_in; (void)out_size;

    mm_kernel<<<NBLK, NTHR>>>(sig, Bext, MsatP, srcP, probeP, finalP, out);
}